// round 12
// baseline (speedup 1.0000x reference)
#include <cuda_runtime.h>
#include <cstdint>

#define NTH 256
#define WLS 128
#define R 8
typedef unsigned long long u64;

// 4 MB transposed+padded W_lin: g_wlinT[k][a] = W_lin[a][k], a padded 100->128 with zeros
__device__ float g_wlinT[8192 * 128];

__global__ void __launch_bounds__(256)
transpose_wlin_kernel(const float* __restrict__ W_lin) {
    int idx = blockIdx.x * 256 + threadIdx.x;   // 0 .. 8192*128-1
    int a = idx & 127;
    int k = idx >> 7;
    g_wlinT[idx] = (a < 100) ? W_lin[a * 8192 + k] : 0.0f;
}

static __device__ __forceinline__ float sigf(float v) {
    return __fdividef(1.0f, 1.0f + __expf(-v));
}
static __device__ __forceinline__ float tanh_acc(float v) {
    return 1.0f - __fdividef(2.0f, __expf(2.0f * v) + 1.0f);
}
static __device__ __forceinline__ u64 pack2(float s) {
    u64 r; asm("mov.b64 %0, {%1, %1};" : "=l"(r) : "f"(s)); return r;
}
static __device__ __forceinline__ u64 pack2f(float a, float b) {
    u64 r; asm("mov.b64 %0, {%1, %2};" : "=l"(r) : "f"(a), "f"(b)); return r;
}
static __device__ __forceinline__ float2 unpk(u64 v) {
    float2 f; asm("mov.b64 {%0, %1}, %2;" : "=f"(f.x), "=f"(f.y) : "l"(v)); return f;
}
static __device__ __forceinline__ void fma2(u64 &d, u64 w, u64 s) {
    asm("fma.rn.f32x2 %0, %1, %2, %0;" : "+l"(d) : "l"(w), "l"(s));
}
static __device__ __forceinline__ void cp16(uint32_t dst, const void* src) {
    asm volatile("cp.async.cg.shared.global [%0], [%1], 16;" :: "r"(dst), "l"(src));
}

__global__ void __launch_bounds__(NTH, 1)
lstm_fused_kernel(const float* __restrict__ x,      // [8192,128,32]
                  const float* __restrict__ W_ih,   // [256,32]
                  const float* __restrict__ W_hh,   // [256,64]
                  const float* __restrict__ b_ih,   // [256]
                  const float* __restrict__ b_hh,   // [256]
                  const float* __restrict__ b_lin,  // [100]
                  float* __restrict__ out)          // [8192,100]
{
    constexpr int T = 128, F = 32, H = 64;
    extern __shared__ float smem[];
    float4* s_wih  = (float4*)smem;              // [F][2][32]   : 2048 float4
    float4* s_whh  = (float4*)(smem + 8192);     // [H][2][32]   : 4096 float4
    float4* s_bias = (float4*)(smem + 24576);    // [2][32]      : 64 float4
    float*  s_wlin = smem + 24832;               // [64][WLS=128]: 8192 floats

    const int tid  = threadIdx.x;
    const int lane = tid & 31;
    const int warp = tid >> 5;

    // ---- one-time staging: permuted weights so gate g = lane + 32*(4m+c) ----
    for (int u = tid; u < F * 64; u += NTH) {
        int f = u >> 6, m = (u >> 5) & 1, l = u & 31;
        float4 v;
        v.x = W_ih[(l + 32 * (4 * m + 0)) * F + f];
        v.y = W_ih[(l + 32 * (4 * m + 1)) * F + f];
        v.z = W_ih[(l + 32 * (4 * m + 2)) * F + f];
        v.w = W_ih[(l + 32 * (4 * m + 3)) * F + f];
        s_wih[u] = v;
    }
    for (int u = tid; u < H * 64; u += NTH) {
        int j = u >> 6, m = (u >> 5) & 1, l = u & 31;
        float4 v;
        v.x = W_hh[(l + 32 * (4 * m + 0)) * H + j];
        v.y = W_hh[(l + 32 * (4 * m + 1)) * H + j];
        v.z = W_hh[(l + 32 * (4 * m + 2)) * H + j];
        v.w = W_hh[(l + 32 * (4 * m + 3)) * H + j];
        s_whh[u] = v;
    }
    if (tid < 64) {
        int m = (tid >> 5) & 1, l = tid & 31;
        float4 v;
        v.x = b_ih[l + 32 * (4 * m + 0)] + b_hh[l + 32 * (4 * m + 0)];
        v.y = b_ih[l + 32 * (4 * m + 1)] + b_hh[l + 32 * (4 * m + 1)];
        v.z = b_ih[l + 32 * (4 * m + 2)] + b_hh[l + 32 * (4 * m + 2)];
        v.w = b_ih[l + 32 * (4 * m + 3)] + b_hh[l + 32 * (4 * m + 3)];
        s_bias[tid] = v;
    }

    // R rows per warp, 64 rows per block, grid 128 => single wave
    const int row0 = blockIdx.x * (8 * R) + warp * R;

    float h_lo[R], h_hi[R], c_lo[R], c_hi[R], xv[R], xn[R];
    u64 lgA[R], lgB[R];

    u64 blA = 0, blB = 0;
    if (lane < 25) {
        float4 b = *(const float4*)(b_lin + 4 * lane);
        blA = pack2f(b.x, b.y);
        blB = pack2f(b.z, b.w);
    }
    const float* xb = x + (size_t)row0 * T * F + lane;
    #pragma unroll
    for (int r = 0; r < R; ++r) {
        h_lo[r] = h_hi[r] = c_lo[r] = c_hi[r] = 0.f;
        lgA[r] = blA; lgB[r] = blB;
        xn[r] = xb[r * T * F];
    }

    const uint32_t wlin_smem = (uint32_t)__cvta_generic_to_shared(s_wlin);

    __syncthreads();

    for (int t = 0; t < T; ++t) {
        // issue staging of this step's W_lin slice: linear 32KB copy (8x 16B/thread)
        {
            const char* src = (const char*)(g_wlinT + t * 8192) + tid * 16;
            uint32_t dst = wlin_smem + tid * 16;
            #pragma unroll
            for (int k = 0; k < 8; ++k)
                cp16(dst + k * 4096, src + k * 4096);
            asm volatile("cp.async.commit_group;" ::: "memory");
        }

        #pragma unroll
        for (int r = 0; r < R; ++r) xv[r] = xn[r];
        int tn = (t + 1 < T) ? (t + 1) : t;
        #pragma unroll
        for (int r = 0; r < R; ++r) xn[r] = xb[r * T * F + tn * F];

        // gate accumulators (packed pairs): A0=(i_lo,i_hi) A1=(f_lo,f_hi) B0=(g_lo,g_hi) B1=(o_lo,o_hi)
        u64 aA0[R], aA1[R], aB0[R], aB1[R];
        {
            ulonglong2 bb0 = ((const ulonglong2*)s_bias)[lane];
            ulonglong2 bb1 = ((const ulonglong2*)s_bias)[32 + lane];
            #pragma unroll
            for (int r = 0; r < R; ++r) {
                aA0[r] = bb0.x; aA1[r] = bb0.y;
                aB0[r] = bb1.x; aB1[r] = bb1.y;
            }
        }

        #pragma unroll 4
        for (int f = 0; f < F; ++f) {
            ulonglong2 w0 = *(const ulonglong2*)(s_wih + f * 64 + lane);
            ulonglong2 w1 = *(const ulonglong2*)(s_wih + f * 64 + 32 + lane);
            #pragma unroll
            for (int r = 0; r < R; ++r) {
                u64 s2 = pack2(__shfl_sync(0xffffffffu, xv[r], f));
                fma2(aA0[r], w0.x, s2); fma2(aA1[r], w0.y, s2);
                fma2(aB0[r], w1.x, s2); fma2(aB1[r], w1.y, s2);
            }
        }
        #pragma unroll 2
        for (int j = 0; j < 32; ++j) {
            ulonglong2 w0 = *(const ulonglong2*)(s_whh + j * 64 + lane);
            ulonglong2 w1 = *(const ulonglong2*)(s_whh + j * 64 + 32 + lane);
            ulonglong2 W0 = *(const ulonglong2*)(s_whh + (j + 32) * 64 + lane);
            ulonglong2 W1 = *(const ulonglong2*)(s_whh + (j + 32) * 64 + 32 + lane);
            #pragma unroll
            for (int r = 0; r < R; ++r) {
                u64 s2 = pack2(__shfl_sync(0xffffffffu, h_lo[r], j));
                fma2(aA0[r], w0.x, s2); fma2(aA1[r], w0.y, s2);
                fma2(aB0[r], w1.x, s2); fma2(aB1[r], w1.y, s2);
                u64 u2 = pack2(__shfl_sync(0xffffffffu, h_hi[r], j));
                fma2(aA0[r], W0.x, u2); fma2(aA1[r], W0.y, u2);
                fma2(aB0[r], W1.x, u2); fma2(aB1[r], W1.y, u2);
            }
        }

        // elementwise LSTM update
        #pragma unroll
        for (int r = 0; r < R; ++r) {
            float2 iv = unpk(aA0[r]);
            float2 fv = unpk(aA1[r]);
            float2 gv = unpk(aB0[r]);
            float2 ov = unpk(aB1[r]);
            c_lo[r] = sigf(fv.x) * c_lo[r] + sigf(iv.x) * tanh_acc(gv.x);
            c_hi[r] = sigf(fv.y) * c_hi[r] + sigf(iv.y) * tanh_acc(gv.y);
            h_lo[r] = sigf(ov.x) * tanh_acc(c_lo[r]);
            h_hi[r] = sigf(ov.y) * tanh_acc(c_hi[r]);
        }

        asm volatile("cp.async.wait_group 0;" ::: "memory");
        __syncthreads();  // s_wlin staged

        // online logits accumulation: lg[a] += h_t[j] * W_lin[a, t*64+j]
        #pragma unroll 2
        for (int j = 0; j < 32; ++j) {
            ulonglong2 wl = *(const ulonglong2*)(s_wlin + j * WLS + 4 * lane);
            ulonglong2 wh = *(const ulonglong2*)(s_wlin + (j + 32) * WLS + 4 * lane);
            #pragma unroll
            for (int r = 0; r < R; ++r) {
                u64 v2 = pack2(__shfl_sync(0xffffffffu, h_lo[r], j));
                fma2(lgA[r], wl.x, v2); fma2(lgB[r], wl.y, v2);
                u64 u2 = pack2(__shfl_sync(0xffffffffu, h_hi[r], j));
                fma2(lgA[r], wh.x, u2); fma2(lgB[r], wh.y, u2);
            }
        }

        __syncthreads();  // protect s_wlin before next overwrite
    }

    // ---- softmax over 100 assets, 4 per lane in lanes 0..24 ----
    const float NEG_INF = __int_as_float(0xff800000);
    #pragma unroll
    for (int r = 0; r < R; ++r) {
        float2 pa = unpk(lgA[r]);
        float2 pb = unpk(lgB[r]);
        float m = (lane < 25) ? fmaxf(fmaxf(pa.x, pa.y), fmaxf(pb.x, pb.y)) : NEG_INF;
        #pragma unroll
        for (int off = 16; off; off >>= 1)
            m = fmaxf(m, __shfl_xor_sync(0xffffffffu, m, off));
        float e0 = 0.f, e1 = 0.f, e2 = 0.f, e3 = 0.f, s = 0.f;
        if (lane < 25) {
            e0 = __expf(pa.x - m); e1 = __expf(pa.y - m);
            e2 = __expf(pb.x - m); e3 = __expf(pb.y - m);
            s = (e0 + e1) + (e2 + e3);
        }
        #pragma unroll
        for (int off = 16; off; off >>= 1)
            s += __shfl_xor_sync(0xffffffffu, s, off);
        if (lane < 25) {
            float inv = __fdividef(1.0f, s);
            float4 o = make_float4(e0 * inv, e1 * inv, e2 * inv, e3 * inv);
            *(float4*)(out + (size_t)(row0 + r) * 100 + 4 * lane) = o;
        }
    }
}

extern "C" void kernel_launch(void* const* d_in, const int* in_sizes, int n_in,
                              void* d_out, int out_size) {
    const float* x     = (const float*)d_in[0];
    const float* W_ih  = (const float*)d_in[1];
    const float* W_hh  = (const float*)d_in[2];
    const float* b_ih  = (const float*)d_in[3];
    const float* b_hh  = (const float*)d_in[4];
    const float* W_lin = (const float*)d_in[5];
    const float* b_lin = (const float*)d_in[6];
    float* out = (float*)d_out;

    transpose_wlin_kernel<<<8192 * 128 / 256, 256>>>(W_lin);

    const int smem_bytes = (24832 + 64 * WLS) * 4;  // 132096
    cudaFuncSetAttribute(lstm_fused_kernel,
                         cudaFuncAttributeMaxDynamicSharedMemorySize, smem_bytes);
    lstm_fused_kernel<<<128, NTH, smem_bytes>>>(x, W_ih, W_hh, b_ih, b_hh,
                                                b_lin, out);
}